// round 1
// baseline (speedup 1.0000x reference)
#include <cuda_runtime.h>

// ---------------- problem constants ----------------
#define NB   4
#define SEQ  2048
#define NH   16
#define DEP  64
#define DM   1024
#define MROWS (NB*SEQ)          // 8192
#define BQ   128                // attention q-tile
#define BKV  64                 // attention kv-tile

// ---------------- scratch (static device globals: alloc-guard legal) ----------------
__device__ float g_qh [(size_t)NB*NH*SEQ*DEP];   // [B,H,S,dep]
__device__ float g_kh [(size_t)NB*NH*SEQ*DEP];
__device__ float g_vh [(size_t)NB*NH*SEQ*DEP];
__device__ float g_ctx[(size_t)MROWS*DM];        // [B,S,D] (heads interleaved)

// ---------------- fast exp: all fixed-latency ops (no MUFU) ----------------
// e^x via 2^(x*log2e); round-to-int by magic constant; deg-5 poly on [-0.5,0.5].
// Accurate to ~2e-6 rel; valid for x <= ~0 (softmax args), clamped at 2^-126.
__device__ __forceinline__ float fexp(float x) {
    float z  = fmaxf(x * 1.4426950408889634f, -126.0f);
    float zi = z + 12582912.0f;                 // 1.5 * 2^23
    int   n  = __float_as_int(zi);              // low bits hold round(z) (+offset, shifts out)
    float f  = zi - 12582912.0f;                // round(z) as float
    float r  = z - f;                           // [-0.5, 0.5]
    float p  = 0.0013333558f;
    p = fmaf(p, r, 0.0096181291f);
    p = fmaf(p, r, 0.0555041087f);
    p = fmaf(p, r, 0.2402265069f);
    p = fmaf(p, r, 0.6931471806f);
    p = fmaf(p, r, 1.0f);
    int bits = __float_as_int(p) + (int)((unsigned)n << 23);
    return __int_as_float(bits);
}

// ---------------- GEMM: C[M,1024] = A[M,1024] @ W[1024,1024]^T + bias ----------------
// BM=128, BN=64, BK=16, 256 threads, 8x4 micro-tile.
// headsplit=1: store C[m, n] -> qh[b, h=n/64, s, d=n%64]  (BN=64 => h == blockIdx.x)
__global__ void __launch_bounds__(256) gemm_bias_kernel(
    const float* __restrict__ A, const float* __restrict__ W,
    const float* __restrict__ bias, float* __restrict__ C, int headsplit)
{
    __shared__ float As[16][136];   // [k][m], pad 8 (16B-aligned rows)
    __shared__ float Bs[16][68];    // [k][n], pad 4

    const int K = DM;
    int tid = threadIdx.x;
    int tx = tid & 15, ty = tid >> 4;
    int bx = blockIdx.x, by = blockIdx.y;

    const float* Ab = A + (size_t)by * 128 * K;
    const float* Wb = W + (size_t)bx * 64  * K;

    float acc[8][4];
#pragma unroll
    for (int i = 0; i < 8; i++)
#pragma unroll
        for (int j = 0; j < 4; j++) acc[i][j] = 0.f;

    for (int k0 = 0; k0 < K; k0 += 16) {
#pragma unroll
        for (int q = 0; q < 2; q++) {
            int idx = tid * 2 + q;
            int r = idx >> 2, c4 = (idx & 3) * 4;
            float4 v = *(const float4*)(Ab + (size_t)r * K + k0 + c4);
            As[c4+0][r] = v.x; As[c4+1][r] = v.y; As[c4+2][r] = v.z; As[c4+3][r] = v.w;
        }
        {
            int r = tid >> 2, c4 = (tid & 3) * 4;
            float4 v = *(const float4*)(Wb + (size_t)r * K + k0 + c4);
            Bs[c4+0][r] = v.x; Bs[c4+1][r] = v.y; Bs[c4+2][r] = v.z; Bs[c4+3][r] = v.w;
        }
        __syncthreads();
#pragma unroll
        for (int kk = 0; kk < 16; kk++) {
            float4 a0 = *(const float4*)&As[kk][ty*8];
            float4 a1 = *(const float4*)&As[kk][ty*8 + 4];
            float4 b  = *(const float4*)&Bs[kk][tx*4];
            float av[8] = {a0.x,a0.y,a0.z,a0.w,a1.x,a1.y,a1.z,a1.w};
            float bv[4] = {b.x,b.y,b.z,b.w};
#pragma unroll
            for (int i = 0; i < 8; i++)
#pragma unroll
                for (int j = 0; j < 4; j++)
                    acc[i][j] = fmaf(av[i], bv[j], acc[i][j]);
        }
        __syncthreads();
    }

    float4 bb = *(const float4*)(bias + bx*64 + tx*4);
    float bvv[4] = {bb.x, bb.y, bb.z, bb.w};
#pragma unroll
    for (int i = 0; i < 8; i++) {
        int m = by*128 + ty*8 + i;
        float4 o;
        o.x = acc[i][0] + bvv[0];
        o.y = acc[i][1] + bvv[1];
        o.z = acc[i][2] + bvv[2];
        o.w = acc[i][3] + bvv[3];
        if (headsplit) {
            int bb_ = m >> 11;          // m / SEQ
            int s   = m & (SEQ - 1);
            float* dst = C + (((size_t)(bb_*NH + bx) * SEQ + s) * DEP) + tx*4;
            *(float4*)dst = o;
        } else {
            *(float4*)(C + (size_t)m * DM + bx*64 + tx*4) = o;
        }
    }
}

// ---------------- flash attention (fp32, online softmax, FFMA exp) ----------------
// Block: 128 q-rows x one (b,h). 256 threads: thread (ty,tx) owns 8 rows x 4 cols.
// Smem: Qt[d][r] 64x136, Kt[d][c] 64x68, Vs[k][d] 64x64, Ps[r][c] 128x68.
#define ATTN_SMEM_FLOATS (64*136 + 64*68 + 64*64 + 128*68)

__global__ void __launch_bounds__(256, 2) attn_kernel(
    const float* __restrict__ Qh, const float* __restrict__ Kh,
    const float* __restrict__ Vh, float* __restrict__ Ctx)
{
    extern __shared__ float sm[];
    float* Qt = sm;                       // [64][136]
    float* Kt = Qt + 64*136;              // [64][68]
    float* Vs = Kt + 64*68;               // [64][64]
    float* Ps = Vs + 64*64;               // [128][68]

    int tid = threadIdx.x;
    int tx = tid & 15, ty = tid >> 4;
    int qt = blockIdx.x;                  // 0..15
    int h  = blockIdx.y, b = blockIdx.z;

    const float* Qb = Qh + (((size_t)(b*NH + h)) * SEQ + (size_t)qt*BQ) * DEP;
    const float* Kb = Kh + ((size_t)(b*NH + h)) * SEQ * DEP;
    const float* Vb = Vh + ((size_t)(b*NH + h)) * SEQ * DEP;

    // load Q tile transposed: 128 rows x 64 d
#pragma unroll
    for (int q = 0; q < 8; q++) {
        int idx = q*256 + tid;
        int r = idx >> 4, d4 = (idx & 15) * 4;
        float4 v = *(const float4*)(Qb + (size_t)r * DEP + d4);
        Qt[(d4+0)*136 + r] = v.x;
        Qt[(d4+1)*136 + r] = v.y;
        Qt[(d4+2)*136 + r] = v.z;
        Qt[(d4+3)*136 + r] = v.w;
    }

    float O[8][4];
    float mrow[8], lrow[8];
#pragma unroll
    for (int i = 0; i < 8; i++) {
        mrow[i] = -1e30f; lrow[i] = 0.f;
#pragma unroll
        for (int j = 0; j < 4; j++) O[i][j] = 0.f;
    }
    const float scale = 0.125f;           // 1/sqrt(64)

    for (int kt = 0; kt < SEQ/BKV; kt++) {
        __syncthreads();   // prior PV done (and Qt ready on iter 0)

        // load K transposed + V natural
#pragma unroll
        for (int q = 0; q < 4; q++) {
            int idx = q*256 + tid;
            int r = idx >> 4, d4 = (idx & 15) * 4;
            float4 kv = *(const float4*)(Kb + (size_t)(kt*BKV + r) * DEP + d4);
            Kt[(d4+0)*68 + r] = kv.x;
            Kt[(d4+1)*68 + r] = kv.y;
            Kt[(d4+2)*68 + r] = kv.z;
            Kt[(d4+3)*68 + r] = kv.w;
            float4 vv = *(const float4*)(Vb + (size_t)(kt*BKV + r) * DEP + d4);
            *(float4*)&Vs[r*64 + d4] = vv;
        }
        __syncthreads();

        // scores: S = Q @ K^T (8x4 per thread over d=64)
        float s_[8][4];
#pragma unroll
        for (int i = 0; i < 8; i++)
#pragma unroll
            for (int j = 0; j < 4; j++) s_[i][j] = 0.f;
#pragma unroll 4
        for (int d = 0; d < 64; d++) {
            float4 a0 = *(const float4*)&Qt[d*136 + ty*8];
            float4 a1 = *(const float4*)&Qt[d*136 + ty*8 + 4];
            float4 bk = *(const float4*)&Kt[d*68 + tx*4];
            float av[8] = {a0.x,a0.y,a0.z,a0.w,a1.x,a1.y,a1.z,a1.w};
            float bv[4] = {bk.x,bk.y,bk.z,bk.w};
#pragma unroll
            for (int i = 0; i < 8; i++)
#pragma unroll
                for (int j = 0; j < 4; j++)
                    s_[i][j] = fmaf(av[i], bv[j], s_[i][j]);
        }

        // online softmax update per row; P -> smem
#pragma unroll
        for (int i = 0; i < 8; i++) {
            float tmax = fmaxf(fmaxf(s_[i][0], s_[i][1]),
                               fmaxf(s_[i][2], s_[i][3])) * scale;
#pragma unroll
            for (int mk = 8; mk >= 1; mk >>= 1)
                tmax = fmaxf(tmax, __shfl_xor_sync(0xffffffffu, tmax, mk));
            float mnew  = fmaxf(mrow[i], tmax);
            float alpha = fexp(mrow[i] - mnew);
            mrow[i] = mnew;
            float p0 = fexp(fmaf(s_[i][0], scale, -mnew));
            float p1 = fexp(fmaf(s_[i][1], scale, -mnew));
            float p2 = fexp(fmaf(s_[i][2], scale, -mnew));
            float p3 = fexp(fmaf(s_[i][3], scale, -mnew));
            float rs = (p0 + p1) + (p2 + p3);
#pragma unroll
            for (int mk = 8; mk >= 1; mk >>= 1)
                rs += __shfl_xor_sync(0xffffffffu, rs, mk);
            lrow[i] = lrow[i] * alpha + rs;
#pragma unroll
            for (int j = 0; j < 4; j++) O[i][j] *= alpha;
            *(float4*)&Ps[(ty*8 + i)*68 + tx*4] = make_float4(p0, p1, p2, p3);
        }
        __syncthreads();

        // O += P @ V
#pragma unroll 4
        for (int k = 0; k < 64; k++) {
            float pf[8];
#pragma unroll
            for (int i = 0; i < 8; i++) pf[i] = Ps[(ty*8 + i)*68 + k];
            float4 v = *(const float4*)&Vs[k*64 + tx*4];
            float vv[4] = {v.x, v.y, v.z, v.w};
#pragma unroll
            for (int i = 0; i < 8; i++)
#pragma unroll
                for (int j = 0; j < 4; j++)
                    O[i][j] = fmaf(pf[i], vv[j], O[i][j]);
        }
    }

    // epilogue: normalize, write ctx in [B,S,D] (heads interleaved)
#pragma unroll
    for (int i = 0; i < 8; i++) {
        float inv = 1.f / lrow[i];
        int s = qt*BQ + ty*8 + i;
        float4 o = make_float4(O[i][0]*inv, O[i][1]*inv, O[i][2]*inv, O[i][3]*inv);
        *(float4*)(Ctx + ((size_t)(b*SEQ + s) * DM) + h*DEP + tx*4) = o;
    }
}

// ---------------- launch ----------------
extern "C" void kernel_launch(void* const* d_in, const int* in_sizes, int n_in,
                              void* d_out, int out_size)
{
    const float* q    = (const float*)d_in[0];
    const float* k    = (const float*)d_in[1];
    const float* v    = (const float*)d_in[2];
    const float* wq_w = (const float*)d_in[3];
    const float* wq_b = (const float*)d_in[4];
    const float* wk_w = (const float*)d_in[5];
    const float* wk_b = (const float*)d_in[6];
    const float* wv_w = (const float*)d_in[7];
    const float* wv_b = (const float*)d_in[8];
    const float* wo_w = (const float*)d_in[9];
    const float* wo_b = (const float*)d_in[10];
    float* out = (float*)d_out;

    float *qh, *kh, *vh, *ctx;
    cudaGetSymbolAddress((void**)&qh,  g_qh);
    cudaGetSymbolAddress((void**)&kh,  g_kh);
    cudaGetSymbolAddress((void**)&vh,  g_vh);
    cudaGetSymbolAddress((void**)&ctx, g_ctx);

    const int attn_smem = ATTN_SMEM_FLOATS * (int)sizeof(float);  // ~101 KB
    cudaFuncSetAttribute(attn_kernel,
                         cudaFuncAttributeMaxDynamicSharedMemorySize, attn_smem);

    dim3 gblk(256), ggrid(DM/64, MROWS/128);      // (16, 64)
    gemm_bias_kernel<<<ggrid, gblk>>>(q, wq_w, wq_b, qh, 1);
    gemm_bias_kernel<<<ggrid, gblk>>>(k, wk_w, wk_b, kh, 1);
    gemm_bias_kernel<<<ggrid, gblk>>>(v, wv_w, wv_b, vh, 1);

    dim3 ablk(256), agrid(SEQ/BQ, NH, NB);        // (16, 16, 4)
    attn_kernel<<<agrid, ablk, attn_smem>>>(qh, kh, vh, ctx);

    gemm_bias_kernel<<<ggrid, gblk>>>(ctx, wo_w, wo_b, out, 0);
}